// round 14
// baseline (speedup 1.0000x reference)
#include <cuda_runtime.h>
#include <cuda_fp16.h>
#include <cstdint>

#define N_TOKENS   1000000
#define NFEAT      128
#define NCLUST     64
#define TILE_TOK   64
#define NUM_TILES  ((N_TOKENS + TILE_TOK - 1) / TILE_TOK)   // 15625
#define GRID_MAIN  296
#define GB_STRIDE  16
#define CAP        256
#define NSLOTS     (GRID_MAIN * 256)
#define SCAP       4096

// ---- smem layout ----
#define SM_XHI   0                           // 2 x 16KB fp16 token tiles (double buffer)
#define SM_CHI   32768                       // 16KB fp16 center tile
#define SM_X2E   49152                       // 2 x 64 x float2 (x2, E)
#define SM_KC    50176
#define SM_TOTAL 50192                       // x2 CTAs ~ 98.4KB

__device__ unsigned long long g_best[NCLUST * GB_STRIDE];
__device__ unsigned long long g_cand[(size_t)NSLOTS * CAP];   // (mapL<<32)|(cl<<20)|tok
__device__ unsigned int       g_cnt[NSLOTS];
__device__ unsigned int       g_short[NCLUST * SCAP];
__device__ unsigned int       g_shortcnt[NCLUST];
__device__ unsigned int       g_overflow;

__device__ __forceinline__ uint32_t smem_u32(const void* p) {
    uint32_t a;
    asm("{ .reg .u64 t; cvta.to.shared.u64 t, %1; cvt.u32.u64 %0, t; }" : "=r"(a) : "l"(p));
    return a;
}
#define BAR_GRP(id) asm volatile("bar.sync %0, 128;" :: "r"(id) : "memory")

__device__ __forceinline__ void ldsm4(uint32_t (&r)[4], uint32_t addr) {
    asm volatile("ldmatrix.sync.aligned.m8n8.x4.shared.b16 {%0,%1,%2,%3}, [%4];"
        : "=r"(r[0]), "=r"(r[1]), "=r"(r[2]), "=r"(r[3]) : "r"(addr));
}
__device__ __forceinline__ void mma16816(float (&d)[4], const uint32_t (&a)[4],
                                         uint32_t b0, uint32_t b1) {
    asm volatile("mma.sync.aligned.m16n8k16.row.col.f32.f16.f16.f32 "
        "{%0,%1,%2,%3}, {%4,%5,%6,%7}, {%8,%9}, {%0,%1,%2,%3};"
        : "+f"(d[0]), "+f"(d[1]), "+f"(d[2]), "+f"(d[3])
        : "r"(a[0]), "r"(a[1]), "r"(a[2]), "r"(a[3]), "r"(b0), "r"(b1));
}
__device__ __forceinline__ unsigned fmap(float f) {
    unsigned u = __float_as_uint(f);
    return (u & 0x80000000u) ? ~u : (u | 0x80000000u);
}
__device__ __forceinline__ uint32_t pack_h2(__half a, __half b) {
    return (uint32_t)__half_as_ushort(a) | ((uint32_t)__half_as_ushort(b) << 16);
}

__global__ void reset_kernel() {
    int i = threadIdx.x;
    if (i < NCLUST) { g_best[i * GB_STRIDE] = 0ull; g_shortcnt[i] = 0u; }
    if (i == 0) g_overflow = 0u;
}

__global__ __launch_bounds__(256, 2)
void cluster_main(const float* __restrict__ x, const float* __restrict__ cc) {
    extern __shared__ char smem[];
    const uint32_t sm = smem_u32(smem);
    const int tid  = threadIdx.x;
    const int wid  = tid >> 5;
    const int lane = tid & 31;

    const int thalf  = wid & 1;              // token half (n dimension, 32 tokens)
    const int cstrip = wid >> 1;             // cluster strip (m dimension, 16 clusters)
    const int rbase  = thalf * 32 + cstrip * 8;   // 8 token rows this warp converts
    const int barid  = 1 + thalf;            // group barrier per token-half
    const int crow   = rbase + (lane >> 2);  // token row this lane converts
    const int cq     = lane & 3;             // feature quarter (32 feats)

    float2* x2e = (float2*)(smem + SM_X2E);
    unsigned* kcm = (unsigned*)(smem + SM_KC);
    if (tid == 0) *kcm = 0u;

    const float4* xg4 = (const float4*)x;

    int ntiles = 0;
    for (int t = blockIdx.x; t < NUM_TILES; t += GRID_MAIN) ++ntiles;

    // ---- prologue: issue LDGs for tile 0 (registers) ----
    float4 pf[8];
    int tile = blockIdx.x;
    {
        int gtok = tile * TILE_TOK + crow;
        if (gtok >= N_TOKENS) gtok = N_TOKENS - 1;
        const float4* src = xg4 + (size_t)gtok * 32 + cq * 8;
        #pragma unroll
        for (int c = 0; c < 8; ++c) pf[c] = src[c];
    }

    // ---- centers: convert hi tile (direct LDG) + |c|^2 max ----
    {
        int rr = tid >> 2, q = tid & 3;
        const float* cg = cc + rr * NFEAT + q * 32;
        float c2h = 0.f;
        #pragma unroll
        for (int c = 0; c < 4; ++c) {
            __half hv[8];
            #pragma unroll
            for (int t = 0; t < 8; ++t) {
                float v = cg[c * 8 + t];
                c2h = fmaf(v, v, c2h);
                hv[t] = __float2half_rn(v);
            }
            uint4 vh;
            vh.x = pack_h2(hv[0], hv[1]); vh.y = pack_h2(hv[2], hv[3]);
            vh.z = pack_h2(hv[4], hv[5]); vh.w = pack_h2(hv[6], hv[7]);
            uint32_t phys = (uint32_t)rr * 256
                          + (uint32_t)(((q * 4 + c) ^ (rr & 7)) * 16);
            *(uint4*)(smem + SM_CHI + phys) = vh;
        }
        float c2 = c2h + __shfl_xor_sync(0xffffffffu, c2h, 1);
        c2 += __shfl_xor_sync(0xffffffffu, c2, 2);
        if (q == 0) atomicMax(kcm, __float_as_uint(c2));
    }
    __syncthreads();
    const float kconst = 1.25f * 0.001953125f * sqrtf(__uint_as_float(*kcm));

    // ---- hoist center (A) fragments for all 8 k-steps: 32 regs, constant ----
    uint32_t aFk[8][4];
    {
        const int rA = cstrip * 16 + (lane & 15);
        const int kh = lane >> 4;
        #pragma unroll
        for (int k = 0; k < 8; ++k) {
            int ca = 2 * k + kh;
            ldsm4(aFk[k], sm + SM_CHI + (uint32_t)(rA * 256 + ((ca ^ (rA & 7)) * 16)));
        }
    }

    // B (token) ldsm addressing
    const int rB0 = thalf * 32 + (lane & 7) + ((lane >> 4) & 1) * 8;
    const int khB = (lane >> 3) & 1;

    // lane's clusters / tokens in the accumulator
    const int cl0 = cstrip * 16 + (lane >> 2);     // and cl0+8
    float rminU[2] = {__int_as_float(0x7f800000), __int_as_float(0x7f800000)};

    const uint32_t slot = (uint32_t)blockIdx.x * 256 + tid;
    unsigned long long* cbuf = g_cand + (size_t)slot * CAP;
    unsigned cnt = 0;

    for (int it = 0; it < ntiles; ++it, tile += GRID_MAIN) {
        const int tokBase = tile * TILE_TOK;
        const int buf = it & 1;
        const uint32_t xbase = sm + SM_XHI + (uint32_t)buf * 16384;

        // ---- convert register tile -> XHI[buf]; fused x^2 + E ----
        {
            float ss = 0.f;
            #pragma unroll
            for (int c = 0; c < 4; ++c) {
                float e[8];
                *(float4*)(e)     = pf[2 * c];
                *(float4*)(e + 4) = pf[2 * c + 1];
                __half hv[8];
                #pragma unroll
                for (int t = 0; t < 8; ++t) {
                    float v = e[t];
                    ss = fmaf(v, v, ss);
                    hv[t] = __float2half_rn(v);
                }
                uint4 vh;
                vh.x = pack_h2(hv[0], hv[1]); vh.y = pack_h2(hv[2], hv[3]);
                vh.z = pack_h2(hv[4], hv[5]); vh.w = pack_h2(hv[6], hv[7]);
                uint32_t phys = (uint32_t)crow * 256
                              + (uint32_t)(((cq * 4 + c) ^ (crow & 7)) * 16);
                *(uint4*)(xbase + phys - sm + (size_t)(uintptr_t)smem) = vh;
            }
            float tot = ss + __shfl_xor_sync(0xffffffffu, ss, 1);
            tot += __shfl_xor_sync(0xffffffffu, tot, 2);
            if (cq == 0)
                x2e[buf * 64 + crow] = make_float2(tot, fmaf(kconst, sqrtf(tot), 1e-4f));
        }

        // ---- issue LDGs for next tile (hidden under MMA) ----
        if (it + 1 < ntiles) {
            int gtok = (tile + GRID_MAIN) * TILE_TOK + crow;
            if (gtok >= N_TOKENS) gtok = N_TOKENS - 1;
            const float4* src = xg4 + (size_t)gtok * 32 + cq * 8;
            #pragma unroll
            for (int c = 0; c < 8; ++c) pf[c] = src[c];
        }

        BAR_GRP(barid);   // token-half converted; also fences prior tile's reads

        // ---- MMA: 8 k-steps; A (centers) from registers, B (tokens) ldsm ----
        float d[4][4];
        #pragma unroll
        for (int nt = 0; nt < 4; ++nt)
            #pragma unroll
            for (int i = 0; i < 4; ++i) d[nt][i] = 0.f;

        #pragma unroll
        for (int k = 0; k < 8; ++k) {
            uint32_t bF[2][4];
            const int cbk = 2 * k + khB;
            #pragma unroll
            for (int np = 0; np < 2; ++np) {
                int r = rB0 + np * 16;
                ldsm4(bF[np], xbase + (uint32_t)(r * 256 + ((cbk ^ (r & 7)) * 16)));
            }
            mma16816(d[0], aFk[k], bF[0][0], bF[0][1]);
            mma16816(d[1], aFk[k], bF[0][2], bF[0][3]);
            mma16816(d[2], aFk[k], bF[1][0], bF[1][1]);
            mma16816(d[3], aFk[k], bF[1][2], bF[1][3]);
        }

        // ---- epilogue: rows=clusters, cols=tokens; interval collection ----
        #pragma unroll
        for (int nt = 0; nt < 4; ++nt) {
            #pragma unroll
            for (int p = 0; p < 2; ++p) {
                const int tloc = thalf * 32 + nt * 8 + 2 * (lane & 3) + p;
                const int gtok = tokBase + tloc;
                if (gtok < N_TOKENS) {
                    const float2 xe = x2e[buf * 64 + tloc];
                    #pragma unroll
                    for (int j = 0; j < 2; ++j) {
                        float s = fmaf(-2.f, d[nt][j * 2 + p], xe.x);
                        float U = s + xe.y;
                        float L = s - xe.y;
                        if (U < rminU[j]) rminU[j] = U;
                        if (L <= rminU[j]) {
                            if (cnt < CAP)
                                cbuf[cnt] = ((unsigned long long)fmap(L) << 32)
                                          | ((unsigned long long)(cl0 + j * 8) << 20)
                                          | (unsigned)gtok;
                            ++cnt;
                        }
                    }
                }
            }
        }
    }

    g_cnt[slot] = (cnt > CAP) ? CAP : cnt;
    if (cnt > CAP) atomicOr(&g_overflow, 1u);

    #pragma unroll
    for (int j = 0; j < 2; ++j) {
        float v = rminU[j];
        v = fminf(v, __shfl_xor_sync(0xffffffffu, v, 1));
        v = fminf(v, __shfl_xor_sync(0xffffffffu, v, 2));
        if ((lane & 3) == 0) {
            unsigned long long key = ~(((unsigned long long)fmap(v) << 32));
            atomicMax(&g_best[(cl0 + j * 8) * GB_STRIDE], key);
        }
    }
}

// pass 2a: filter candidates against global min-U, bucket by cluster
__global__ void filter_kernel() {
    const uint32_t slot = (uint32_t)blockIdx.x * 256 + threadIdx.x;
    const unsigned n = g_cnt[slot];
    const unsigned long long* cbuf = g_cand + (size_t)slot * CAP;
    for (unsigned i = 0; i < n; ++i) {
        unsigned long long e = cbuf[i];
        unsigned mapL = (unsigned)(e >> 32);
        unsigned cl   = (unsigned)(e >> 20) & 63u;
        unsigned tok  = (unsigned)(e & 0xFFFFFu);
        unsigned gU   = (unsigned)((~g_best[cl * GB_STRIDE]) >> 32);
        if (mapL <= gU) {
            unsigned pos = atomicAdd(&g_shortcnt[cl], 1u);
            if (pos < SCAP) g_short[cl * SCAP + pos] = tok;
            else atomicOr(&g_overflow, 1u);
        }
    }
}

// pass 2b: warp-parallel exact (double) rescore, emit winner row
__global__ void gather_rescore(const float* __restrict__ x,
                               const float* __restrict__ cc,
                               float* __restrict__ out) {
    __shared__ float ck[NFEAT];
    __shared__ double wbd[8];
    __shared__ unsigned wbt[8];
    __shared__ unsigned wtok_s;
    const int k = blockIdx.x;
    const int tid = threadIdx.x;
    const int wid = tid >> 5;
    const int lane = tid & 31;
    if (tid < NFEAT) ck[tid] = cc[k * NFEAT + tid];
    __syncthreads();

    double bd = 1.0e300;
    unsigned bt = 0xFFFFFFFFu;
    const unsigned ovf = g_overflow;
    unsigned n = g_shortcnt[k];
    if (n > SCAP) n = SCAP;

    if (ovf || n == 0) {
        for (unsigned t = tid; t < N_TOKENS; t += 256) {
            double acc = 0.0;
            const float* xr = x + (size_t)t * NFEAT;
            for (int d = 0; d < NFEAT; ++d) {
                double df = (double)xr[d] - (double)ck[d];
                acc += df * df;
            }
            if (acc < bd || (acc == bd && t < bt)) { bd = acc; bt = t; }
        }
        #pragma unroll
        for (int off = 16; off > 0; off >>= 1) {
            double od = __shfl_down_sync(0xffffffffu, bd, off);
            unsigned ot = __shfl_down_sync(0xffffffffu, bt, off);
            if (od < bd || (od == bd && ot < bt)) { bd = od; bt = ot; }
        }
    } else {
        for (unsigned i = wid; i < n; i += 8) {
            unsigned t = g_short[k * SCAP + i];
            const float4* xr = (const float4*)(x + (size_t)t * NFEAT);
            float4 v = xr[lane];
            const float* c4 = ck + lane * 4;
            double acc = 0.0;
            double d0 = (double)v.x - (double)c4[0]; acc += d0 * d0;
            double d1 = (double)v.y - (double)c4[1]; acc += d1 * d1;
            double d2 = (double)v.z - (double)c4[2]; acc += d2 * d2;
            double d3 = (double)v.w - (double)c4[3]; acc += d3 * d3;
            #pragma unroll
            for (int off = 16; off > 0; off >>= 1)
                acc += __shfl_down_sync(0xffffffffu, acc, off);
            acc = __shfl_sync(0xffffffffu, acc, 0);
            if (acc < bd || (acc == bd && t < bt)) { bd = acc; bt = t; }
        }
    }

    if (lane == 0) { wbd[wid] = bd; wbt[wid] = bt; }
    __syncthreads();
    if (tid == 0) {
        double fb = wbd[0]; unsigned ft = wbt[0];
        #pragma unroll
        for (int w = 1; w < 8; ++w) {
            if (wbd[w] < fb || (wbd[w] == fb && wbt[w] < ft)) { fb = wbd[w]; ft = wbt[w]; }
        }
        wtok_s = ft;
    }
    __syncthreads();
    unsigned w = wtok_s;
    if (tid < NFEAT) out[k * NFEAT + tid] = x[(size_t)w * NFEAT + tid];
}

extern "C" void kernel_launch(void* const* d_in, const int* in_sizes, int n_in,
                              void* d_out, int out_size) {
    const float* x;
    const float* cc;
    if (n_in >= 2 && in_sizes[0] == NCLUST * NFEAT) {
        cc = (const float*)d_in[0];
        x  = (const float*)d_in[1];
    } else {
        x  = (const float*)d_in[0];
        cc = (const float*)d_in[1];
    }
    float* out = (float*)d_out;

    cudaFuncSetAttribute(cluster_main,
                         cudaFuncAttributeMaxDynamicSharedMemorySize, SM_TOTAL);

    reset_kernel<<<1, 64>>>();
    cluster_main<<<GRID_MAIN, 256, SM_TOTAL>>>(x, cc);
    filter_kernel<<<GRID_MAIN, 256>>>();
    gather_rescore<<<NCLUST, 256>>>(x, cc, out);
}

// round 15
// speedup vs baseline: 1.5279x; 1.5279x over previous
#include <cuda_runtime.h>
#include <cuda_fp16.h>
#include <cstdint>

#define N_TOKENS   1000000
#define NFEAT      128
#define NCLUST     64
#define TILE_TOK   64
#define NUM_TILES  ((N_TOKENS + TILE_TOK - 1) / TILE_TOK)   // 15625
#define GRID_MAIN  296
#define GB_STRIDE  16
#define CAP        256
#define NSLOTS     (GRID_MAIN * 256)
#define SCAP       4096

// ---- smem layout ----
#define SM_RAW   0                           // 2 x 32KB fp32 staging
#define SM_XHI   65536                       // 64 x 256B fp16 (single buffer)
#define SM_CHI   81920                       // 64 x 256B fp16 centers
#define SM_X2E   98304                       // 64 x float2 (x2, E)
#define SM_KC    98816
#define SM_TOTAL 98832                       // x2 CTAs ~ 197.7KB

__device__ unsigned long long g_best[NCLUST * GB_STRIDE];
__device__ unsigned long long g_cand[(size_t)NSLOTS * CAP];   // (mapL<<32)|(cl<<20)|tok
__device__ unsigned int       g_cnt[NSLOTS];
__device__ unsigned int       g_short[NCLUST * SCAP];
__device__ unsigned int       g_shortcnt[NCLUST];
__device__ unsigned int       g_overflow;

__device__ __forceinline__ uint32_t smem_u32(const void* p) {
    uint32_t a;
    asm("{ .reg .u64 t; cvta.to.shared.u64 t, %1; cvt.u32.u64 %0, t; }" : "=r"(a) : "l"(p));
    return a;
}
__device__ __forceinline__ void cp_async16(uint32_t dst, const void* src) {
    asm volatile("cp.async.cg.shared.global [%0], [%1], 16;" :: "r"(dst), "l"(src));
}
#define CP_COMMIT() asm volatile("cp.async.commit_group;" ::: "memory")
#define CP_WAIT1()  asm volatile("cp.async.wait_group 1;" ::: "memory")
#define BAR_GRP(id) asm volatile("bar.sync %0, 128;" :: "r"(id) : "memory")

__device__ __forceinline__ void ldsm4(uint32_t (&r)[4], uint32_t addr) {
    asm volatile("ldmatrix.sync.aligned.m8n8.x4.shared.b16 {%0,%1,%2,%3}, [%4];"
        : "=r"(r[0]), "=r"(r[1]), "=r"(r[2]), "=r"(r[3]) : "r"(addr));
}
__device__ __forceinline__ void mma16816(float (&d)[4], const uint32_t (&a)[4],
                                         uint32_t b0, uint32_t b1) {
    asm volatile("mma.sync.aligned.m16n8k16.row.col.f32.f16.f16.f32 "
        "{%0,%1,%2,%3}, {%4,%5,%6,%7}, {%8,%9}, {%0,%1,%2,%3};"
        : "+f"(d[0]), "+f"(d[1]), "+f"(d[2]), "+f"(d[3])
        : "r"(a[0]), "r"(a[1]), "r"(a[2]), "r"(a[3]), "r"(b0), "r"(b1));
}
__device__ __forceinline__ unsigned fmap(float f) {
    unsigned u = __float_as_uint(f);
    return (u & 0x80000000u) ? ~u : (u | 0x80000000u);
}
__device__ __forceinline__ uint32_t h2pack(float a, float b) {
    __half2 h = __floats2half2_rn(a, b);
    return *reinterpret_cast<uint32_t*>(&h);
}
// raw-staging swizzle (R13): bijective in dq per row; conflict-free LDS/STS
__device__ __forceinline__ uint32_t raw_phys(int row, int dq) {
    uint32_t mask = (uint32_t)((((dq >> 3) & 3) ^ ((row >> 1) & 3)) | ((row & 1) << 2));
    return (uint32_t)(dq ^ (int)mask) * 16u;
}

__global__ void reset_kernel() {
    int i = threadIdx.x;
    if (i < NCLUST) { g_best[i * GB_STRIDE] = 0ull; g_shortcnt[i] = 0u; }
    if (i == 0) g_overflow = 0u;
}

__global__ __launch_bounds__(256, 2)
void cluster_main(const float* __restrict__ x, const float* __restrict__ cc) {
    extern __shared__ char smem[];
    const uint32_t sm = smem_u32(smem);
    const int tid  = threadIdx.x;
    const int wid  = tid >> 5;
    const int lane = tid & 31;

    const int thalf  = wid & 1;               // token half (B / n dimension)
    const int cstrip = wid >> 1;               // cluster strip (A / m dimension)
    const int rbase  = thalf * 32 + cstrip * 8;   // 8 token rows this warp stages+converts
    const int barid  = 1 + thalf;
    const int crow   = rbase + (lane >> 2);
    const int cq     = lane & 3;

    float2* x2e = (float2*)(smem + SM_X2E);
    unsigned* kcm = (unsigned*)(smem + SM_KC);
    if (tid == 0) *kcm = 0u;

    const float4* xg4 = (const float4*)x;

    int ntiles = 0;
    for (int t = blockIdx.x; t < NUM_TILES; t += GRID_MAIN) ++ntiles;

    auto issue_rows = [&](int tile_idx, int buf) {
        const int tokBase = tile_idx * TILE_TOK;
        const uint32_t base = sm + SM_RAW + (uint32_t)buf * 32768;
        #pragma unroll
        for (int i = 0; i < 8; ++i) {
            int tl = rbase + i;
            int gtok = tokBase + tl;
            if (gtok >= N_TOKENS) gtok = N_TOKENS - 1;
            uint32_t dst = base + (uint32_t)tl * 512 + raw_phys(tl, lane);
            cp_async16(dst, xg4 + (size_t)gtok * 32 + lane);
        }
    };

    int tile = blockIdx.x;
    if (ntiles > 0) issue_rows(tile, 0);
    CP_COMMIT();
    __syncthreads();                           // kcm zero visible

    // ---- centers: convert hi tile + |c|^2 max ----
    {
        int rr = tid >> 2, q = tid & 3;
        const float* cg = cc + rr * NFEAT + q * 32;
        float c2h = 0.f;
        #pragma unroll
        for (int c = 0; c < 4; ++c) {
            float e[8];
            #pragma unroll
            for (int t = 0; t < 8; ++t) {
                float v = cg[c * 8 + t];
                e[t] = v;
                c2h = fmaf(v, v, c2h);
            }
            uint4 vh;
            vh.x = h2pack(e[0], e[1]); vh.y = h2pack(e[2], e[3]);
            vh.z = h2pack(e[4], e[5]); vh.w = h2pack(e[6], e[7]);
            uint32_t phys = (uint32_t)rr * 256
                          + (uint32_t)(((q * 4 + c) ^ (rr & 7)) * 16);
            *(uint4*)(smem + SM_CHI + phys) = vh;
        }
        float c2 = c2h + __shfl_xor_sync(0xffffffffu, c2h, 1);
        c2 += __shfl_xor_sync(0xffffffffu, c2, 2);
        if (q == 0) atomicMax(kcm, __float_as_uint(c2));
    }
    __syncthreads();
    const float kconst = 1.25f * 0.001953125f * sqrtf(__uint_as_float(*kcm));

    // ---- hoist center (A) fragments for all 8 k-steps (32 regs, constant) ----
    uint32_t aFk[8][4];
    {
        const int rA = cstrip * 16 + (lane & 15);
        const int kh = lane >> 4;
        #pragma unroll
        for (int k = 0; k < 8; ++k) {
            int ca = 2 * k + kh;
            ldsm4(aFk[k], sm + SM_CHI + (uint32_t)(rA * 256 + ((ca ^ (rA & 7)) * 16)));
        }
    }

    const int rB0 = thalf * 32 + (lane & 7) + ((lane >> 4) & 1) * 8;
    const int khB = (lane >> 3) & 1;
    const int cl0 = cstrip * 16 + (lane >> 2);       // clusters cl0, cl0+8

    float rminU[2] = {__int_as_float(0x7f800000), __int_as_float(0x7f800000)};

    const uint32_t slot = (uint32_t)blockIdx.x * 256 + tid;
    unsigned long long* cbuf = g_cand + (size_t)slot * CAP;
    unsigned cnt = 0;

    for (int it = 0; it < ntiles; ++it, tile += GRID_MAIN) {
        const int tokBase = tile * TILE_TOK;
        const int buf = it & 1;

        if (it + 1 < ntiles) issue_rows(tile + GRID_MAIN, buf ^ 1);
        CP_COMMIT();
        CP_WAIT1();

        // ---- convert own rows raw[buf] -> XHI; fused x^2 + E ----
        {
            const char* raw = smem + SM_RAW + (size_t)buf * 32768 + (size_t)crow * 512;
            float ss = 0.f;
            #pragma unroll
            for (int c = 0; c < 4; ++c) {
                float e[8];
                int d0 = cq * 8 + 2 * c;
                *(float4*)(e)     = *(const float4*)(raw + raw_phys(crow, d0));
                *(float4*)(e + 4) = *(const float4*)(raw + raw_phys(crow, d0 + 1));
                #pragma unroll
                for (int t = 0; t < 8; ++t) ss = fmaf(e[t], e[t], ss);
                uint4 vh;
                vh.x = h2pack(e[0], e[1]); vh.y = h2pack(e[2], e[3]);
                vh.z = h2pack(e[4], e[5]); vh.w = h2pack(e[6], e[7]);
                uint32_t phys = (uint32_t)crow * 256
                              + (uint32_t)(((cq * 4 + c) ^ (crow & 7)) * 16);
                *(uint4*)(smem + SM_XHI + phys) = vh;
            }
            float tot = ss + __shfl_xor_sync(0xffffffffu, ss, 1);
            tot += __shfl_xor_sync(0xffffffffu, tot, 2);
            if (cq == 0)
                x2e[crow] = make_float2(tot, fmaf(kconst, sqrtf(tot), 1e-4f));
        }
        BAR_GRP(barid);   // token-half converted

        // ---- MMA: 8 k-steps; A (centers) from regs, B (tokens) ldsm ----
        float d[4][4];
        #pragma unroll
        for (int nt = 0; nt < 4; ++nt)
            #pragma unroll
            for (int i = 0; i < 4; ++i) d[nt][i] = 0.f;

        #pragma unroll
        for (int k = 0; k < 8; ++k) {
            uint32_t bF[2][4];
            const int cbk = 2 * k + khB;
            #pragma unroll
            for (int np = 0; np < 2; ++np) {
                int r = rB0 + np * 16;
                ldsm4(bF[np], sm + SM_XHI + (uint32_t)(r * 256 + ((cbk ^ (r & 7)) * 16)));
            }
            mma16816(d[0], aFk[k], bF[0][0], bF[0][1]);
            mma16816(d[1], aFk[k], bF[0][2], bF[0][3]);
            mma16816(d[2], aFk[k], bF[1][0], bF[1][1]);
            mma16816(d[3], aFk[k], bF[1][2], bF[1][3]);
        }

        // ---- screened epilogue ----
        {
            // lane's 8 tokens (shared across both cluster columns)
            float xv[8], Ev[8];
            float Emax = 0.f;
            #pragma unroll
            for (int t = 0; t < 8; ++t) {
                const int nt = t >> 1, p = t & 1;
                const int tloc = thalf * 32 + nt * 8 + 2 * (lane & 3) + p;
                float2 xe = x2e[tloc];
                xv[t] = xe.x; Ev[t] = xe.y;
                Emax = fmaxf(Emax, xe.y);
            }
            #pragma unroll
            for (int j = 0; j < 2; ++j) {
                float s[8];
                #pragma unroll
                for (int t = 0; t < 8; ++t)
                    s[t] = fmaf(-2.f, d[t >> 1][j * 2 + (t & 1)], xv[t]);
                float m01 = fminf(s[0], s[1]), m23 = fminf(s[2], s[3]);
                float m45 = fminf(s[4], s[5]), m67 = fminf(s[6], s[7]);
                float minS = fminf(fminf(m01, m23), fminf(m45, m67));
                // valid (loose) upper bound on min U over these tokens
                rminU[j] = fminf(rminU[j], minS + Emax);
                if (minS - Emax <= rminU[j]) {
                    // slow path: exact per-element intervals
                    #pragma unroll
                    for (int t = 0; t < 8; ++t) {
                        const int nt = t >> 1, p = t & 1;
                        const int tloc = thalf * 32 + nt * 8 + 2 * (lane & 3) + p;
                        const int gtok = tokBase + tloc;
                        float U = s[t] + Ev[t];
                        float L = s[t] - Ev[t];
                        if (U < rminU[j]) rminU[j] = U;
                        if (L <= rminU[j] && gtok < N_TOKENS) {
                            if (cnt < CAP)
                                cbuf[cnt] = ((unsigned long long)fmap(L) << 32)
                                          | ((unsigned long long)(cl0 + j * 8) << 20)
                                          | (unsigned)gtok;
                            ++cnt;
                        }
                    }
                }
            }
        }
        BAR_GRP(barid);   // reads of XHI done before next convert
    }

    g_cnt[slot] = (cnt > CAP) ? CAP : cnt;
    if (cnt > CAP) atomicOr(&g_overflow, 1u);

    #pragma unroll
    for (int j = 0; j < 2; ++j) {
        float v = rminU[j];
        v = fminf(v, __shfl_xor_sync(0xffffffffu, v, 1));
        v = fminf(v, __shfl_xor_sync(0xffffffffu, v, 2));
        if ((lane & 3) == 0) {
            unsigned long long key = ~(((unsigned long long)fmap(v) << 32));
            atomicMax(&g_best[(cl0 + j * 8) * GB_STRIDE], key);
        }
    }
}

// pass 2a: filter candidates against global min-U, bucket by cluster
__global__ void filter_kernel() {
    const uint32_t slot = (uint32_t)blockIdx.x * 256 + threadIdx.x;
    const unsigned n = g_cnt[slot];
    const unsigned long long* cbuf = g_cand + (size_t)slot * CAP;
    for (unsigned i = 0; i < n; ++i) {
        unsigned long long e = cbuf[i];
        unsigned mapL = (unsigned)(e >> 32);
        unsigned cl   = (unsigned)(e >> 20) & 63u;
        unsigned tok  = (unsigned)(e & 0xFFFFFu);
        unsigned gU   = (unsigned)((~g_best[cl * GB_STRIDE]) >> 32);
        if (mapL <= gU) {
            unsigned pos = atomicAdd(&g_shortcnt[cl], 1u);
            if (pos < SCAP) g_short[cl * SCAP + pos] = tok;
            else atomicOr(&g_overflow, 1u);
        }
    }
}

// pass 2b: warp-parallel exact (double) rescore, emit winner row
__global__ void gather_rescore(const float* __restrict__ x,
                               const float* __restrict__ cc,
                               float* __restrict__ out) {
    __shared__ float ck[NFEAT];
    __shared__ double wbd[8];
    __shared__ unsigned wbt[8];
    __shared__ unsigned wtok_s;
    const int k = blockIdx.x;
    const int tid = threadIdx.x;
    const int wid = tid >> 5;
    const int lane = tid & 31;
    if (tid < NFEAT) ck[tid] = cc[k * NFEAT + tid];
    __syncthreads();

    double bd = 1.0e300;
    unsigned bt = 0xFFFFFFFFu;
    const unsigned ovf = g_overflow;
    unsigned n = g_shortcnt[k];
    if (n > SCAP) n = SCAP;

    if (ovf || n == 0) {
        for (unsigned t = tid; t < N_TOKENS; t += 256) {
            double acc = 0.0;
            const float* xr = x + (size_t)t * NFEAT;
            for (int d = 0; d < NFEAT; ++d) {
                double df = (double)xr[d] - (double)ck[d];
                acc += df * df;
            }
            if (acc < bd || (acc == bd && t < bt)) { bd = acc; bt = t; }
        }
        #pragma unroll
        for (int off = 16; off > 0; off >>= 1) {
            double od = __shfl_down_sync(0xffffffffu, bd, off);
            unsigned ot = __shfl_down_sync(0xffffffffu, bt, off);
            if (od < bd || (od == bd && ot < bt)) { bd = od; bt = ot; }
        }
    } else {
        for (unsigned i = wid; i < n; i += 8) {
            unsigned t = g_short[k * SCAP + i];
            const float4* xr = (const float4*)(x + (size_t)t * NFEAT);
            float4 v = xr[lane];
            const float* c4 = ck + lane * 4;
            double acc = 0.0;
            double d0 = (double)v.x - (double)c4[0]; acc += d0 * d0;
            double d1 = (double)v.y - (double)c4[1]; acc += d1 * d1;
            double d2 = (double)v.z - (double)c4[2]; acc += d2 * d2;
            double d3 = (double)v.w - (double)c4[3]; acc += d3 * d3;
            #pragma unroll
            for (int off = 16; off > 0; off >>= 1)
                acc += __shfl_down_sync(0xffffffffu, acc, off);
            acc = __shfl_sync(0xffffffffu, acc, 0);
            if (acc < bd || (acc == bd && t < bt)) { bd = acc; bt = t; }
        }
    }

    if (lane == 0) { wbd[wid] = bd; wbt[wid] = bt; }
    __syncthreads();
    if (tid == 0) {
        double fb = wbd[0]; unsigned ft = wbt[0];
        #pragma unroll
        for (int w = 1; w < 8; ++w) {
            if (wbd[w] < fb || (wbd[w] == fb && wbt[w] < ft)) { fb = wbd[w]; ft = wbt[w]; }
        }
        wtok_s = ft;
    }
    __syncthreads();
    unsigned w = wtok_s;
    if (tid < NFEAT) out[k * NFEAT + tid] = x[(size_t)w * NFEAT + tid];
}

extern "C" void kernel_launch(void* const* d_in, const int* in_sizes, int n_in,
                              void* d_out, int out_size) {
    const float* x;
    const float* cc;
    if (n_in >= 2 && in_sizes[0] == NCLUST * NFEAT) {
        cc = (const float*)d_in[0];
        x  = (const float*)d_in[1];
    } else {
        x  = (const float*)d_in[0];
        cc = (const float*)d_in[1];
    }
    float* out = (float*)d_out;

    cudaFuncSetAttribute(cluster_main,
                         cudaFuncAttributeMaxDynamicSharedMemorySize, SM_TOTAL);

    reset_kernel<<<1, 64>>>();
    cluster_main<<<GRID_MAIN, 256, SM_TOTAL>>>(x, cc);
    filter_kernel<<<GRID_MAIN, 256>>>();
    gather_rescore<<<NCLUST, 256>>>(x, cc, out);
}